// round 5
// baseline (speedup 1.0000x reference)
#include <cuda_runtime.h>
#include <cstdint>

// Problem constants (fixed by the reference)
#define B_    64
#define T_    24
#define NV_   1024
#define C_    64
#define DPW_  7
#define TPD_  288
#define TILE_   (C_ * T_)        // 1536 floats = 6144 bytes per (b,n) slab
#define TILE4_  (TILE_ / 4)      // 384 float4
#define THREADS_ 384             // one float4 lane per thread
#define ITEMS_  (B_ * NV_)       // 65536 (b, vertex) work items
#define GRID_   740              // 148 SMs x 5 resident CTAs -> exactly one wave

__global__ __launch_bounds__(THREADS_)
void dte_kernel(const int* __restrict__ t,
                const float* __restrict__ W,
                float* __restrict__ out) {
    __shared__ float e[TILE_];
    __shared__ int dow_s[T_];
    __shared__ int tod_s[T_];

    const int tid = threadIdx.x;

    // Even contiguous split of ITEMS_ across gridDim.x persistent blocks.
    const long long g = gridDim.x;
    int n   = (int)(((long long)blockIdx.x       * ITEMS_) / g);
    int end = (int)(((long long)(blockIdx.x + 1) * ITEMS_) / g);

    while (n < end) {
        const int b     = n >> 10;                        // item / NV_
        const int b_end = min(end, (b + 1) << 10);

        // ---- build tile for this b (<=2 times per block) ----
        __syncthreads();   // previous segment's stores done reading e
        if (tid < T_) {
            int dow = t[(b * T_ + tid) * 2 + 0] % DPW_;
            int tod = t[(b * T_ + tid) * 2 + 1] % TPD_;
            dow_s[tid] = dow * C_;
            tod_s[tid] = (DPW_ + tod) * C_;
        }
        __syncthreads();
        #pragma unroll
        for (int idx = tid; idx < TILE_; idx += THREADS_) {
            int c  = idx / T_;
            int ti = idx - c * T_;
            e[idx] = W[dow_s[ti] + c] + W[tod_s[ti] + c];
        }
        __syncthreads();

        // ---- broadcast: each thread owns one float4, streams it to all n ----
        const float4 val = reinterpret_cast<const float4*>(e)[tid];
        float4* o = reinterpret_cast<float4*>(out) + (size_t)n * TILE4_ + tid;

        int cnt = b_end - n;
        // unrolled-by-4 independent stores for MLP
        for (; cnt >= 4; cnt -= 4) {
            o[0 * TILE4_] = val;
            o[1 * TILE4_] = val;
            o[2 * TILE4_] = val;
            o[3 * TILE4_] = val;
            o += 4 * TILE4_;
        }
        for (; cnt > 0; cnt--) {
            *o = val;
            o += TILE4_;
        }
        n = b_end;
    }
}

extern "C" void kernel_launch(void* const* d_in, const int* in_sizes, int n_in,
                              void* d_out, int out_size) {
    const int*   t = (const int*)d_in[0];    // [B, T, 2] int32
    const float* W = (const float*)d_in[1];  // [DPW+TPD, C] float32
    float* out = (float*)d_out;              // [B, N, C, T] float32

    dte_kernel<<<GRID_, THREADS_>>>(t, W, out);
}